// round 10
// baseline (speedup 1.0000x reference)
#include <cuda_runtime.h>
#include <cstdint>

// SpikeFP64ScaleBy2K — soft-logic FP64 scale-by-2^k collapsed to integer bit ops.
// R9: champion R4 body with ROWS_PER_WARP 4 -> 8 (16 front-batched LDG.64,
// MLP 16). Tests the one untried axis: RAISING the occ x MLP latency-hiding
// product (R4: 82%x8=656; here ~62%x16~=1000). Decode chain byte-identical
// to the verified champion (rel_err 0 across R1-R8).

static constexpr int ROWS_PER_WARP = 8;
static constexpr int WARPS_PER_BLOCK = 8;
static constexpr int BLOCK_THREADS = WARPS_PER_BLOCK * 32;

__global__ void __launch_bounds__(BLOCK_THREADS)
scale2k_kernel(const uint2* __restrict__ x2,
               const uint2* __restrict__ k2,
               uint2* __restrict__ o2,
               int nrows)
{
    const int lane = threadIdx.x & 31;
    const int warp = blockIdx.x * WARPS_PER_BLOCK + (threadIdx.x >> 5);
    const int row0 = warp * ROWS_PER_WARP;
    if (row0 >= nrows) return;  // warp-uniform exit

    // ---- per-lane weights (hoisted; lane j holds bit positions 2j, 2j+1) ----
    const unsigned wE_x = (lane >= 1 && lane <= 5) ? (1u << (11 - 2 * lane)) : 0u;
    const unsigned wE_y = (lane <= 5) ? (1u << (10 - 2 * lane)) : 0u;
    const unsigned wV_x = (lane >= 6 && lane <= 13) ? (1u << (26 - 2 * lane)) : 0u;
    const unsigned wV_y = (lane >= 6 && lane <= 12) ? (1u << (25 - 2 * lane)) : 0u;
    const unsigned w1x = (wE_x << 16) | wV_x;
    const unsigned w1y = (wE_y << 16) | wV_y;
    const unsigned w2kx = (lane == 0) ? (1u << 20) : (1u << 12);
    const unsigned w2ky = 1u << 12;
    const unsigned sh_x = (unsigned)(11 - 2 * lane) & 31u;
    const unsigned sh_y = (unsigned)(10 - 2 * lane) & 31u;
    const bool lane_le5 = (lane <= 5);
    const bool lane_ge1 = (lane >= 1);

    // ---- front-batch loads: 16 independent LDG.64 per lane (MLP 16) ----
    uint2 xv[ROWS_PER_WARP];
    uint2 kv[ROWS_PER_WARP];
#pragma unroll
    for (int r = 0; r < ROWS_PER_WARP; ++r) {
        if (row0 + r < nrows) {  // warp-uniform
            const long idx = (long)(row0 + r) * 32 + lane;
            xv[r] = __ldg(&x2[idx]);
            kv[r] = __ldg(&k2[idx]);
        }
    }

#pragma unroll
    for (int r = 0; r < ROWS_PER_WARP; ++r) {
        if (row0 + r >= nrows) break;  // warp-uniform

        // Inputs are exactly 0.0f / 1.0f: bit = bits >> 29.
        const unsigned bkx = kv[r].x >> 29;
        const unsigned bky = kv[r].y >> 29;
        const unsigned bxx = xv[r].x >> 29;
        const unsigned bxy = xv[r].y >> 29;

        const unsigned c1 = bkx * w1x + bky * w1y;
        const unsigned c2 = bxx * wE_x + bxy * wE_y + bkx * w2kx + bky * w2ky;

        const unsigned r1 = __reduce_add_sync(0xFFFFFFFFu, c1);
        const unsigned r2 = __reduce_add_sync(0xFFFFFFFFu, c2);

        // ---- uniform scalar chain (bit-exact across all rounds) ----
        const unsigned e_k   = r1 >> 16;
        const unsigned val   = 0x8000u | (r1 & 0xFFFFu);
        const unsigned t     = (~(e_k + 1025u)) & 15u;
        const unsigned k_abs = (val >> t) & 0x7FFu;
        const unsigned s_k   = (r2 >> 20) & 1u;
        const unsigned k_fin = s_k ? ((0u - k_abs) & 0x7FFu) : k_abs;
        const unsigned e_x   = r2 & 0x7FFu;
        const unsigned e_new = (e_x + k_fin) & 0x7FFu;
        const bool nz        = ((r2 >> 12) & 0xFFu) != 0u;

        // ---- patch exponent field (bits 1..11 -> lanes 0..5), branch-free ----
        const unsigned px = ((e_new >> sh_x) & 1u) * 0x3F800000u;
        const unsigned py = ((e_new >> sh_y) & 1u) * 0x3F800000u;

        uint2 ov = xv[r];
        const bool patch = nz && lane_le5;
        ov.x = (patch && lane_ge1) ? px : ov.x;
        ov.y = patch ? py : ov.y;

        const long idx = (long)(row0 + r) * 32 + lane;
        o2[idx] = ov;
    }
}

extern "C" void kernel_launch(void* const* d_in, const int* in_sizes, int n_in,
                              void* d_out, int out_size) {
    const uint2* x2 = (const uint2*)d_in[0];
    const uint2* k2 = (const uint2*)d_in[1];
    uint2* o2 = (uint2*)d_out;

    const int nrows = in_sizes[0] / 64;
    const int nwarps = (nrows + ROWS_PER_WARP - 1) / ROWS_PER_WARP;
    const int nblocks = (nwarps + WARPS_PER_BLOCK - 1) / WARPS_PER_BLOCK;

    scale2k_kernel<<<nblocks, BLOCK_THREADS>>>(x2, k2, o2, nrows);
}

// round 11
// speedup vs baseline: 1.0375x; 1.0375x over previous
#include <cuda_runtime.h>
#include <cstdint>

// SpikeFP64ScaleBy2K — soft-logic FP64 scale-by-2^k collapsed to integer bit ops.
// FINAL champion (R4 shape): 115.9us timed / 112.3us kernel, DRAM 86.4%,
// 6.85 TB/s — at the measured mixed-stream (2R:1W) HBM ceiling.
//
// Every design element validated by an isolated experiment across 10 rounds:
//   - warp-per-row, lane j holds bits {2j,2j+1} via one coalesced LDG.64
//   - ROWS_PER_WARP=4 / MLP=8: measured optimum of the occ x MLP curve
//     (RPW=2 -> 118.4us, RPW=4 -> 115.9us, RPW=8 -> 119.5us)
//   - bit extract: inputs are exactly 0.0f/1.0f -> bit = bits>>29 (single SHF)
//   - field decode: 2x __reduce_add_sync of packed per-lane weights
//       r1 = sum((e_k_w<<16)|val_w)  -> e_k = r1>>16, top-15 mantissa = r1&0x7FFF
//       r2 = sum(e_x_w | nz<<12 | sign<<20)
//   - uniform scalar chain: t = ~(e_k+1025)&15; k_abs = (0x8000|frac)>>t & 0x7FF;
//     two's-complement negate if s_k; e_new = (e_x + k_final) & 0x7FF
//   - patch exponent bits 1..11 (lanes 0..5) branch-free via *0x3F800000 (no I2F)
//   - full-grid launch, default cache policy (streaming hints cost regs: regress)
//   - 32 regs, occ ~82% (load-bearing: every occupancy-reducing variant lost)

static constexpr int ROWS_PER_WARP = 4;
static constexpr int WARPS_PER_BLOCK = 8;
static constexpr int BLOCK_THREADS = WARPS_PER_BLOCK * 32;

__global__ void __launch_bounds__(BLOCK_THREADS)
scale2k_kernel(const uint2* __restrict__ x2,
               const uint2* __restrict__ k2,
               uint2* __restrict__ o2,
               int nrows)
{
    const int lane = threadIdx.x & 31;
    const int warp = blockIdx.x * WARPS_PER_BLOCK + (threadIdx.x >> 5);
    const int row0 = warp * ROWS_PER_WARP;
    if (row0 >= nrows) return;  // warp-uniform exit

    // ---- per-lane weights (hoisted; lane j holds bit positions 2j, 2j+1) ----
    const unsigned wE_x = (lane >= 1 && lane <= 5) ? (1u << (11 - 2 * lane)) : 0u;
    const unsigned wE_y = (lane <= 5) ? (1u << (10 - 2 * lane)) : 0u;
    const unsigned wV_x = (lane >= 6 && lane <= 13) ? (1u << (26 - 2 * lane)) : 0u;
    const unsigned wV_y = (lane >= 6 && lane <= 12) ? (1u << (25 - 2 * lane)) : 0u;
    const unsigned w1x = (wE_x << 16) | wV_x;
    const unsigned w1y = (wE_y << 16) | wV_y;
    const unsigned w2kx = (lane == 0) ? (1u << 20) : (1u << 12);
    const unsigned w2ky = 1u << 12;
    const unsigned sh_x = (unsigned)(11 - 2 * lane) & 31u;
    const unsigned sh_y = (unsigned)(10 - 2 * lane) & 31u;
    const bool lane_le5 = (lane <= 5);
    const bool lane_ge1 = (lane >= 1);

    // ---- front-batch loads: 8 independent LDG.64 per lane (MLP 8) ----
    uint2 xv[ROWS_PER_WARP];
    uint2 kv[ROWS_PER_WARP];
#pragma unroll
    for (int r = 0; r < ROWS_PER_WARP; ++r) {
        if (row0 + r < nrows) {  // warp-uniform
            const long idx = (long)(row0 + r) * 32 + lane;
            xv[r] = __ldg(&x2[idx]);
            kv[r] = __ldg(&k2[idx]);
        }
    }

#pragma unroll
    for (int r = 0; r < ROWS_PER_WARP; ++r) {
        if (row0 + r >= nrows) break;  // warp-uniform

        // Inputs are exactly 0.0f / 1.0f: bit = bits >> 29.
        const unsigned bkx = kv[r].x >> 29;
        const unsigned bky = kv[r].y >> 29;
        const unsigned bxx = xv[r].x >> 29;
        const unsigned bxy = xv[r].y >> 29;

        const unsigned c1 = bkx * w1x + bky * w1y;
        const unsigned c2 = bxx * wE_x + bxy * wE_y + bkx * w2kx + bky * w2ky;

        const unsigned r1 = __reduce_add_sync(0xFFFFFFFFu, c1);
        const unsigned r2 = __reduce_add_sync(0xFFFFFFFFu, c2);

        // ---- uniform scalar chain (bit-exact, rel_err 0 across all rounds) ----
        const unsigned e_k   = r1 >> 16;
        const unsigned val   = 0x8000u | (r1 & 0xFFFFu);
        const unsigned t     = (~(e_k + 1025u)) & 15u;
        const unsigned k_abs = (val >> t) & 0x7FFu;
        const unsigned s_k   = (r2 >> 20) & 1u;
        const unsigned k_fin = s_k ? ((0u - k_abs) & 0x7FFu) : k_abs;
        const unsigned e_x   = r2 & 0x7FFu;
        const unsigned e_new = (e_x + k_fin) & 0x7FFu;
        const bool nz        = ((r2 >> 12) & 0xFFu) != 0u;

        // ---- patch exponent field (bits 1..11 -> lanes 0..5), branch-free ----
        const unsigned px = ((e_new >> sh_x) & 1u) * 0x3F800000u;
        const unsigned py = ((e_new >> sh_y) & 1u) * 0x3F800000u;

        uint2 ov = xv[r];
        const bool patch = nz && lane_le5;
        ov.x = (patch && lane_ge1) ? px : ov.x;
        ov.y = patch ? py : ov.y;

        const long idx = (long)(row0 + r) * 32 + lane;
        o2[idx] = ov;
    }
}

extern "C" void kernel_launch(void* const* d_in, const int* in_sizes, int n_in,
                              void* d_out, int out_size) {
    const uint2* x2 = (const uint2*)d_in[0];
    const uint2* k2 = (const uint2*)d_in[1];
    uint2* o2 = (uint2*)d_out;

    const int nrows = in_sizes[0] / 64;
    const int nwarps = (nrows + ROWS_PER_WARP - 1) / ROWS_PER_WARP;
    const int nblocks = (nwarps + WARPS_PER_BLOCK - 1) / WARPS_PER_BLOCK;

    scale2k_kernel<<<nblocks, BLOCK_THREADS>>>(x2, k2, o2, nrows);
}